// round 7
// baseline (speedup 1.0000x reference)
#include <cuda_runtime.h>
#include <cstdint>

#define IMAGE_H 200
#define IMAGE_W 200
#define ROW_BYTES (IMAGE_W * 3)               // 600
#define PARTS 4
#define PART_ROWS (IMAGE_H / PARTS)           // 50
#define PART_BYTES (PART_ROWS * ROW_BYTES)    // 30000 smem bytes per tile
#define IMG_ELEMS (IMAGE_H * IMAGE_W * 3)     // 120000 float elems per image
#define THREADS 512

// Fused, quarter-tiled: compose uint8 tile in SMEM (zero + closed-form Bresenham
// + markers, row-filtered), then stream out as float32. 4 blocks/SM resident so
// per-block prologues overlap other blocks' store streams.
__global__ void __launch_bounds__(THREADS) draw_rope_fused(
    const float* __restrict__ x,          // [M, 6] = (x0,y0,x1,y1,x2,y2)
    const float* __restrict__ resolution, // [2]
    const float* __restrict__ origin,     // [2]
    float* __restrict__ out)              // [M, 200, 200, 3] float32
{
    __shared__ unsigned char s_img[PART_BYTES];

    const int m    = blockIdx.x >> 2;       // image index
    const int part = blockIdx.x & 3;        // quarter index
    const int r_lo = part * PART_ROWS;      // first row of this tile
    const int r_hi = r_lo + PART_ROWS;      // one past last row

    // ---- Phase 0: zero smem tile ----
    {
        uint4 z = make_uint4(0u, 0u, 0u, 0u);
        uint4* s4 = reinterpret_cast<uint4*>(s_img);
        const int n16 = PART_BYTES / 16; // 1875
        for (int i = threadIdx.x; i < n16; i += THREADS) s4[i] = z;
    }

    // ---- rope point pixel indices (all threads, registers) ----
    const float res0 = resolution[0];
    const float res1 = resolution[1];
    const float org0 = origin[0];
    const float org1 = origin[1];
    const float* px = x + (size_t)m * 6;

    int rows[3], cols[3];
#pragma unroll
    for (int i = 0; i < 3; i++) {
        float xf = px[2 * i + 0];
        float yf = px[2 * i + 1];
        rows[i] = (int)floorf(yf / res0 + org0);
        cols[i] = (int)floorf(xf / res1 + org1);
    }

    __syncthreads(); // zero-fill complete

    // ---- Phase 1: closed-form Bresenham into smem (row-filtered) ----
    // m_k = floor((2*k*minor + major) / (2*major)), pixels k = 0..major inclusive
#pragma unroll
    for (int s = 0; s < 2; s++) {
        const int c0 = cols[s],     r0 = rows[s];
        const int c1 = cols[s + 1], r1 = rows[s + 1];
        const int dx = abs(c1 - c0);
        const int D  = abs(r1 - r0);
        const int sc = (c0 < c1) ? 1 : -1;
        const int sr = (r0 < r1) ? 1 : -1;
        const bool xmajor = (dx >= D);
        const unsigned major = xmajor ? (unsigned)dx : (unsigned)D;
        const unsigned minor = xmajor ? (unsigned)D  : (unsigned)dx;

        if (major == 0u) {
            if (threadIdx.x == 0 &&
                r0 >= r_lo && r0 < r_hi && (unsigned)c0 < (unsigned)IMAGE_W) {
                unsigned char* q = s_img + ((r0 - r_lo) * IMAGE_W + c0) * 3;
                q[0] = 128; q[1] = 128; q[2] = 128;
            }
        } else {
            const unsigned den = 2u * major;
            for (unsigned k = threadIdx.x; k <= major; k += THREADS) {
                const int qs = (int)((2u * k * minor + major) / den);
                const int c = xmajor ? (c0 + (int)k * sc) : (c0 + qs * sc);
                const int r = xmajor ? (r0 + qs * sr) : (r0 + (int)k * sr);
                if (r >= r_lo && r < r_hi && (unsigned)c < (unsigned)IMAGE_W) {
                    unsigned char* q = s_img + ((r - r_lo) * IMAGE_W + c) * 3;
                    q[0] = 128; q[1] = 128; q[2] = 128;
                }
            }
        }
    }

    __syncthreads(); // line pixels done before marker overwrites

    // ---- Phase 2: endpoint markers (row-filtered), reference order r,r,g ----
    if (threadIdx.x == 0) {
        const unsigned char R[3][3] = { {255, 0, 0}, {255, 0, 0}, {0, 255, 0} };
#pragma unroll
        for (int i = 0; i < 3; i++) {
            int r = rows[i], cidx = cols[i];
            if (r >= r_lo && r < r_hi && (unsigned)cidx < (unsigned)IMAGE_W) {
                unsigned char* q = s_img + ((r - r_lo) * IMAGE_W + cidx) * 3;
                q[0] = R[i][0]; q[1] = R[i][1]; q[2] = R[i][2];
            }
        }
    }

    __syncthreads(); // tile complete in smem

    // ---- Phase 3: stream out as float32 (u8 -> f32, 128-bit stores) ----
    {
        const uint32_t* s32 = reinterpret_cast<const uint32_t*>(s_img);
        float4* o4 = reinterpret_cast<float4*>(
            out + (size_t)m * IMG_ELEMS + (size_t)part * (PART_BYTES));
        const int n4 = PART_BYTES / 4; // 7500
        for (int i = threadIdx.x; i < n4; i += THREADS) {
            uint32_t w = s32[i];
            float4 f;
            f.x = (float)( w        & 0xffu);
            f.y = (float)((w >> 8)  & 0xffu);
            f.z = (float)((w >> 16) & 0xffu);
            f.w = (float)( w >> 24        );
            o4[i] = f;
        }
    }
}

extern "C" void kernel_launch(void* const* d_in, const int* in_sizes, int n_in,
                              void* d_out, int out_size) {
    const float* x          = (const float*)d_in[0]; // [B*T*6] float32
    const float* resolution = (const float*)d_in[1]; // [2]
    const float* origin     = (const float*)d_in[2]; // [2]
    float* out              = (float*)d_out;         // [B,T,200,200,3] float32

    const int M = in_sizes[0] / 6; // B*T = 800 images
    draw_rope_fused<<<M * PARTS, THREADS>>>(x, resolution, origin, out);
}